// round 1
// baseline (speedup 1.0000x reference)
#include <cuda_runtime.h>
#include <cstdint>
#include <cstddef>

#define BATCH 2
#define NTOK 2048
#define CDIM 1152
#define HEADS 16
#define HD 72
#define BH (BATCH*HEADS)      /* 32   */
#define MROWS (BATCH*NTOK)    /* 4096 */
#define K3 (3*CDIM)           /* 3456 */
#define QK_PAD 80             /* padded bytes per q/k row (72 -> 80, zero pad) */
#define ATT_SCALE 0.11785113019775793f  /* 72^-0.5 */

// ---------------- scratch (static device memory; no allocation) ----------------
__device__ float g_qkv[(size_t)MROWS * K3];                          // 56.6 MB
__device__ __align__(16) signed char g_q8[(size_t)BH * NTOK * QK_PAD];
__device__ __align__(16) signed char g_k8[(size_t)BH * NTOK * QK_PAD];
__device__ float g_qs[BH * NTOK];
__device__ float g_ks[BH * NTOK];
__device__ __align__(16) signed char g_v8[(size_t)BH * HD * NTOK];   // [bh][d][m]
__device__ float g_vs[BH * HD];
__device__ float g_logits[(size_t)BH * NTOK * NTOK];                 // 536 MB
__device__ __align__(16) unsigned char g_p8[(size_t)BH * NTOK * NTOK]; // 134 MB
__device__ float g_rowfac[BH * NTOK];
__device__ float g_ctx[(size_t)MROWS * CDIM];                        // 18.9 MB

__device__ __forceinline__ int dp4a_us(unsigned int a, int b, int c) {
    int d;
    asm("dp4a.u32.s32 %0, %1, %2, %3;" : "=r"(d) : "r"(a), "r"(b), "r"(c));
    return d;
}

// ---------------- fp32 NT GEMM: C[M,N] = A[M,K] @ B[N,K]^T (+bias) ----------------
// 128x128 tile, BK=8, 256 threads, 8x8 register tile.
__global__ __launch_bounds__(256) void sgemm128_nt(
    const float* __restrict__ A, const float* __restrict__ B,
    const float* __restrict__ bias, float* __restrict__ C,
    int M, int N, int K)
{
    __shared__ float As[8][128];
    __shared__ float Bs[8][128];
    const int tid  = threadIdx.x;
    const int row0 = blockIdx.y * 128;
    const int col0 = blockIdx.x * 128;
    const int tx = tid & 15;
    const int ty = tid >> 4;
    const int lr = tid >> 1;          // 0..127
    const int lk = (tid & 1) << 2;    // 0 or 4

    const float* Ap = A + (size_t)(row0 + lr) * K + lk;
    const float* Bp = B + (size_t)(col0 + lr) * K + lk;

    float acc[8][8];
#pragma unroll
    for (int i = 0; i < 8; i++)
#pragma unroll
        for (int j = 0; j < 8; j++) acc[i][j] = 0.f;

    for (int k0 = 0; k0 < K; k0 += 8) {
        float4 a4 = *(const float4*)(Ap + k0);
        float4 b4 = *(const float4*)(Bp + k0);
        __syncthreads();
        As[lk + 0][lr] = a4.x; As[lk + 1][lr] = a4.y;
        As[lk + 2][lr] = a4.z; As[lk + 3][lr] = a4.w;
        Bs[lk + 0][lr] = b4.x; Bs[lk + 1][lr] = b4.y;
        Bs[lk + 2][lr] = b4.z; Bs[lk + 3][lr] = b4.w;
        __syncthreads();
#pragma unroll
        for (int kk = 0; kk < 8; kk++) {
            float4 a0 = *(const float4*)&As[kk][ty * 8];
            float4 a1 = *(const float4*)&As[kk][ty * 8 + 4];
            float4 b0 = *(const float4*)&Bs[kk][tx * 8];
            float4 b1 = *(const float4*)&Bs[kk][tx * 8 + 4];
            float ar[8] = {a0.x, a0.y, a0.z, a0.w, a1.x, a1.y, a1.z, a1.w};
            float br[8] = {b0.x, b0.y, b0.z, b0.w, b1.x, b1.y, b1.z, b1.w};
#pragma unroll
            for (int i = 0; i < 8; i++)
#pragma unroll
                for (int j = 0; j < 8; j++)
                    acc[i][j] = fmaf(ar[i], br[j], acc[i][j]);
        }
    }

#pragma unroll
    for (int i = 0; i < 8; i++) {
        int r = row0 + ty * 8 + i;
        float* Cp = C + (size_t)r * N + col0 + tx * 8;
#pragma unroll
        for (int j = 0; j < 8; j++) {
            float v = acc[i][j];
            if (bias) v += bias[col0 + tx * 8 + j];
            Cp[j] = v;
        }
    }
}

// ---------------- per-row symmetric int8 quant of q and k ----------------
// one warp per (t, bh, n) row of 72 values; t=0 -> q, t=1 -> k.
__global__ __launch_bounds__(256) void quant_qk_kernel()
{
    int warp = threadIdx.x >> 5, lane = threadIdx.x & 31;
    int row = blockIdx.x * 8 + warp;           // 0 .. 2*BH*NTOK-1
    int t  = row >> 16;                        // / 65536
    int r  = row & 65535;
    int bh = r >> 11;
    int n  = r & 2047;
    int b = bh >> 4, h = bh & 15;
    const float* src = g_qkv + (size_t)(b * NTOK + n) * K3 + t * CDIM + h * HD;

    float x0 = src[lane];
    float x1 = src[lane + 32];
    float x2 = (lane < 8) ? src[lane + 64] : 0.f;
    float amax = fmaxf(fabsf(x0), fmaxf(fabsf(x1), fabsf(x2)));
#pragma unroll
    for (int s = 16; s; s >>= 1) amax = fmaxf(amax, __shfl_xor_sync(0xffffffffu, amax, s));
    float scale = fmaxf(amax, 1e-8f) / 127.0f;

    signed char* dst = (t ? g_k8 : g_q8) + (size_t)(bh * NTOK + n) * QK_PAD;
    int q0 = min(127, max(-128, (int)rintf(__fdiv_rn(x0, scale))));
    int q1 = min(127, max(-128, (int)rintf(__fdiv_rn(x1, scale))));
    dst[lane]      = (signed char)q0;
    dst[lane + 32] = (signed char)q1;
    if (lane < 8) {
        int q2 = min(127, max(-128, (int)rintf(__fdiv_rn(x2, scale))));
        dst[lane + 64] = (signed char)q2;
    } else if (lane < 16) {
        dst[lane + 64] = 0;   // zero pad bytes 72..79
    }
    if (lane == 0) (t ? g_ks : g_qs)[bh * NTOK + n] = scale;
}

// ---------------- per-channel symmetric int8 quant of v (over tokens) ----------------
// one block per (bh, d); writes transposed layout v8[bh][d][m].
__global__ __launch_bounds__(256) void quant_v_kernel()
{
    int col = blockIdx.x;          // 0 .. BH*HD-1
    int bh = col / HD, d = col % HD;
    int b = bh >> 4, h = bh & 15;
    const float* base = g_qkv + (size_t)b * NTOK * K3 + 2 * CDIM + h * HD + d;

    float vals[8];
    float amax = 0.f;
#pragma unroll
    for (int i = 0; i < 8; i++) {
        vals[i] = base[(size_t)(threadIdx.x + 256 * i) * K3];
        amax = fmaxf(amax, fabsf(vals[i]));
    }
    __shared__ float red[256];
    red[threadIdx.x] = amax;
    __syncthreads();
    for (int s = 128; s >= 1; s >>= 1) {
        if (threadIdx.x < s) red[threadIdx.x] = fmaxf(red[threadIdx.x], red[threadIdx.x + s]);
        __syncthreads();
    }
    float scale = fmaxf(red[0], 1e-8f) / 127.0f;

    signed char* dst = g_v8 + (size_t)(bh * HD + d) * NTOK;
#pragma unroll
    for (int i = 0; i < 8; i++) {
        int m = threadIdx.x + 256 * i;
        int q = min(127, max(-128, (int)rintf(__fdiv_rn(vals[i], scale))));
        dst[m] = (signed char)q;
    }
    if (threadIdx.x == 0) g_vs[bh * HD + d] = scale;
}

// ---------------- int8 QK^T logits GEMM (dp4a), 64x64 tile ----------------
__global__ __launch_bounds__(256) void logits_kernel()
{
    int bh   = blockIdx.z;
    int row0 = blockIdx.y * 64;
    int col0 = blockIdx.x * 64;
    __shared__ int qa[64][21];   // 20 words/row used (+1 pad)
    __shared__ int kb[64][21];

    const int* qbase = (const int*)(g_q8 + (size_t)(bh * NTOK + row0) * QK_PAD);
    const int* kbase = (const int*)(g_k8 + (size_t)(bh * NTOK + col0) * QK_PAD);
    for (int idx = threadIdx.x; idx < 64 * 20; idx += 256) {
        int r = idx / 20, w = idx % 20;
        qa[r][w] = qbase[r * 20 + w];
        kb[r][w] = kbase[r * 20 + w];
    }
    __syncthreads();

    int tx = threadIdx.x & 15, ty = threadIdx.x >> 4;
    int acc[4][4] = {};
#pragma unroll
    for (int w = 0; w < 20; w++) {
        int ra[4], rb[4];
#pragma unroll
        for (int i = 0; i < 4; i++) ra[i] = qa[ty + 16 * i][w];
#pragma unroll
        for (int j = 0; j < 4; j++) rb[j] = kb[tx + 16 * j][w];
#pragma unroll
        for (int i = 0; i < 4; i++)
#pragma unroll
            for (int j = 0; j < 4; j++)
                acc[i][j] = __dp4a(ra[i], rb[j], acc[i][j]);
    }

#pragma unroll
    for (int i = 0; i < 4; i++) {
        int rr = row0 + ty + 16 * i;
        float qs = g_qs[bh * NTOK + rr] * ATT_SCALE;
        float* out = g_logits + ((size_t)bh * NTOK + rr) * NTOK + col0;
#pragma unroll
        for (int j = 0; j < 4; j++) {
            int cc = tx + 16 * j;
            out[cc] = (float)acc[i][j] * qs * g_ks[bh * NTOK + col0 + cc];
        }
    }
}

// ---------------- softmax + unsigned 8-bit quant per row ----------------
// p = round(255*exp(l - max))  (independent of Z); rowfac = (1/Z)/255.
__global__ __launch_bounds__(256) void softmax_kernel()
{
    size_t rowbase = (size_t)blockIdx.x * NTOK;
    const float* lrow = g_logits + rowbase;
    int tid = threadIdx.x;

    float l[8];
    float m = -1e30f;
#pragma unroll
    for (int i = 0; i < 8; i++) {
        l[i] = lrow[tid + 256 * i];
        m = fmaxf(m, l[i]);
    }
    __shared__ float red[256];
    red[tid] = m;
    __syncthreads();
    for (int s = 128; s >= 1; s >>= 1) {
        if (tid < s) red[tid] = fmaxf(red[tid], red[tid + s]);
        __syncthreads();
    }
    m = red[0];
    __syncthreads();

    float e[8];
    float z = 0.f;
#pragma unroll
    for (int i = 0; i < 8; i++) {
        e[i] = expf(l[i] - m);
        z += e[i];
    }
    red[tid] = z;
    __syncthreads();
    for (int s = 128; s >= 1; s >>= 1) {
        if (tid < s) red[tid] += red[tid + s];
        __syncthreads();
    }
    z = red[0];

    unsigned char* prow = g_p8 + rowbase;
#pragma unroll
    for (int i = 0; i < 8; i++) {
        int p = (int)rintf(255.0f * e[i]);
        p = min(255, max(0, p));
        prow[tid + 256 * i] = (unsigned char)p;
    }
    if (tid == 0) g_rowfac[blockIdx.x] = __fdiv_rn(1.0f, z) / 255.0f;
}

// ---------------- PV GEMM: u8 attn map x s8 v (dp4a), 64-row tiles ----------------
// block (72, 4): thread (d, y) accumulates rows y+4r, r=0..15, over K=2048 in 256-m chunks.
__global__ __launch_bounds__(288) void pv_kernel()
{
    int bh = blockIdx.y;
    int b = bh >> 4, h = bh & 15;
    int row0 = blockIdx.x * 64;
    int lin = threadIdx.y * 72 + threadIdx.x;
    int d = threadIdx.x;

    __shared__ int pS[64][68];   // 64 words (= 256 m-bytes) per row (+4 pad)
    __shared__ int vS[72][68];

    const int* pbase = (const int*)(g_p8 + ((size_t)bh * NTOK + row0) * NTOK);   // row pitch 512 words
    const int* vbase = (const int*)(g_v8 + (size_t)bh * HD * NTOK);              // row pitch 512 words

    int acc[16] = {};

    for (int mc = 0; mc < 8; mc++) {
        __syncthreads();
        for (int idx = lin; idx < 64 * 64; idx += 288) {
            int r = idx >> 6, w = idx & 63;
            pS[r][w] = pbase[r * 512 + mc * 64 + w];
        }
        for (int idx = lin; idx < 72 * 64; idx += 288) {
            int r = idx >> 6, w = idx & 63;
            vS[r][w] = vbase[r * 512 + mc * 64 + w];
        }
        __syncthreads();
#pragma unroll
        for (int g = 0; g < 16; g++) {
            int4 vv = *(const int4*)&vS[d][g * 4];
#pragma unroll
            for (int r = 0; r < 16; r++) {
                int4 pp = *(const int4*)&pS[threadIdx.y + 4 * r][g * 4];
                acc[r] = dp4a_us((unsigned)pp.x, vv.x, acc[r]);
                acc[r] = dp4a_us((unsigned)pp.y, vv.y, acc[r]);
                acc[r] = dp4a_us((unsigned)pp.z, vv.z, acc[r]);
                acc[r] = dp4a_us((unsigned)pp.w, vv.w, acc[r]);
            }
        }
    }

    float vsd = g_vs[bh * HD + d];
#pragma unroll
    for (int r = 0; r < 16; r++) {
        int n = row0 + threadIdx.y + 4 * r;
        float val = (float)acc[r] * g_rowfac[bh * NTOK + n] * vsd;
        g_ctx[(size_t)(b * NTOK + n) * CDIM + h * HD + d] = val;
    }
}

// ---------------- launch ----------------
extern "C" void kernel_launch(void* const* d_in, const int* in_sizes, int n_in,
                              void* d_out, int out_size)
{
    const float* x      = (const float*)d_in[0];
    const float* w_qkv  = (const float*)d_in[1];
    const float* w_proj = (const float*)d_in[2];
    const float* b_proj = (const float*)d_in[3];
    float* out = (float*)d_out;
    (void)in_sizes; (void)n_in; (void)out_size;

    void *p_qkv = nullptr, *p_ctx = nullptr;
    cudaGetSymbolAddress(&p_qkv, g_qkv);
    cudaGetSymbolAddress(&p_ctx, g_ctx);

    // 1) QKV projection: [4096,3456] = x[4096,1152] @ w_qkv[3456,1152]^T
    sgemm128_nt<<<dim3(K3 / 128, MROWS / 128), 256>>>(
        x, w_qkv, nullptr, (float*)p_qkv, MROWS, K3, CDIM);

    // 2) quantize q,k per row; v per channel (transposed)
    quant_qk_kernel<<<2 * BH * NTOK / 8, 256>>>();
    quant_v_kernel<<<BH * HD, 256>>>();

    // 3) int8 logits GEMM
    logits_kernel<<<dim3(NTOK / 64, NTOK / 64, BH), 256>>>();

    // 4) softmax + u8 quant
    softmax_kernel<<<BH * NTOK, 256>>>();

    // 5) PV int GEMM -> ctx [B,N,C]
    pv_kernel<<<dim3(NTOK / 64, BH), dim3(72, 4)>>>();

    // 6) output projection + bias
    sgemm128_nt<<<dim3(CDIM / 128, MROWS / 128), 256>>>(
        (const float*)p_ctx, w_proj, b_proj, out, MROWS, CDIM, CDIM);
}

// round 3
// speedup vs baseline: 1.1774x; 1.1774x over previous
#include <cuda_runtime.h>
#include <cuda_bf16.h>
#include <cstdint>
#include <cstddef>

#define BATCH 2
#define NTOK 2048
#define CDIM 1152
#define HEADS 16
#define HD 72
#define BH (BATCH*HEADS)      /* 32   */
#define MROWS (BATCH*NTOK)    /* 4096 */
#define K3 (3*CDIM)           /* 3456 */
#define QK_PAD 80
#define ATT_SCALE 0.11785113019775793f  /* 72^-0.5 */

#define GK CDIM               /* K of both big GEMMs (per segment) */
#define BK 16                 /* K per mma step */
#define CHPS (GK/BK)          /* 72 */
#define NCHUNK (3*CHPS)       /* 216: hi*hi, lo*hi, hi*lo */
#define APAD 24               /* padded smem row stride in bf16 */

// ---------------- scratch (static device memory) ----------------
__device__ float g_qkv[(size_t)MROWS * K3];
__device__ __align__(16) signed char g_q8[(size_t)BH * NTOK * QK_PAD];
__device__ __align__(16) signed char g_k8[(size_t)BH * NTOK * QK_PAD];
__device__ float g_qs[BH * NTOK];
__device__ float g_ks[BH * NTOK];
__device__ __align__(16) signed char g_v8[(size_t)BH * HD * NTOK];   // [bh][d][m]
__device__ float g_vs[BH * HD];
__device__ float g_logits[(size_t)BH * NTOK * NTOK];
__device__ __align__(16) unsigned char g_p8[(size_t)BH * NTOK * NTOK];
__device__ float g_rowfac[BH * NTOK];

// bf16 split operands
__device__ __align__(16) __nv_bfloat16 g_x_hi[(size_t)MROWS * CDIM];
__device__ __align__(16) __nv_bfloat16 g_x_lo[(size_t)MROWS * CDIM];
__device__ __align__(16) __nv_bfloat16 g_wq_hi[(size_t)K3 * CDIM];
__device__ __align__(16) __nv_bfloat16 g_wq_lo[(size_t)K3 * CDIM];
__device__ __align__(16) __nv_bfloat16 g_wp_hi[(size_t)CDIM * CDIM];
__device__ __align__(16) __nv_bfloat16 g_wp_lo[(size_t)CDIM * CDIM];
__device__ __align__(16) __nv_bfloat16 g_ctx_hi[(size_t)MROWS * CDIM];
__device__ __align__(16) __nv_bfloat16 g_ctx_lo[(size_t)MROWS * CDIM];

__device__ __forceinline__ int dp4a_us(unsigned int a, int b, int c) {
    int d;
    asm("dp4a.u32.s32 %0, %1, %2, %3;" : "=r"(d) : "r"(a), "r"(b), "r"(c));
    return d;
}

__device__ __forceinline__ void mma_bf16(float* c, uint32_t a0, uint32_t a1,
                                         uint32_t a2, uint32_t a3,
                                         uint32_t b0, uint32_t b1) {
    asm volatile(
        "mma.sync.aligned.m16n8k16.row.col.f32.bf16.bf16.f32 "
        "{%0,%1,%2,%3}, {%4,%5,%6,%7}, {%8,%9}, {%0,%1,%2,%3};"
        : "+f"(c[0]), "+f"(c[1]), "+f"(c[2]), "+f"(c[3])
        : "r"(a0), "r"(a1), "r"(a2), "r"(a3), "r"(b0), "r"(b1));
}

// ---------------- split fp32 -> bf16 hi + lo ----------------
__global__ __launch_bounds__(256) void split_kernel(const float* __restrict__ s,
                                                    __nv_bfloat16* __restrict__ hi,
                                                    __nv_bfloat16* __restrict__ lo, int n)
{
    int i = blockIdx.x * 256 + threadIdx.x;
    if (i < n) {
        float v = s[i];
        __nv_bfloat16 h = __float2bfloat16_rn(v);
        hi[i] = h;
        lo[i] = __float2bfloat16_rn(v - __bfloat162float(h));
    }
}

// ---------------- HMMA bf16x3 GEMM: C[M,N] = A[M,GK] @ B[N,GK]^T (+bias) ----------------
// 128x128 tile, 256 threads (8 warps as 2x4), each warp 64x32 via m16n8k16.
__global__ __launch_bounds__(256) void hmma_gemm_bf16x3(
    const __nv_bfloat16* __restrict__ Ah, const __nv_bfloat16* __restrict__ Al,
    const __nv_bfloat16* __restrict__ Bh, const __nv_bfloat16* __restrict__ Bl,
    const float* __restrict__ bias, float* __restrict__ C, int ldc)
{
    __shared__ __nv_bfloat16 As[2][128 * APAD];
    __shared__ __nv_bfloat16 Bs[2][128 * APAD];

    const int tid = threadIdx.x;
    const int wid = tid >> 5;
    const int lane = tid & 31;
    const int g  = lane >> 2;     // 0..7
    const int tg = lane & 3;      // 0..3
    const int wm = wid >> 2;      // 0..1 -> 64-row slab
    const int wn = wid & 3;       // 0..3 -> 32-col slab
    const int m0 = blockIdx.y * 128;
    const int n0 = blockIdx.x * 128;

    const int ldrow = tid >> 1;   // 0..127
    const int ldhalf = tid & 1;   // which 8-elem half of the 16-elem K chunk

    float acc[4][4][4];
#pragma unroll
    for (int i = 0; i < 4; i++)
#pragma unroll
        for (int j = 0; j < 4; j++)
#pragma unroll
            for (int q = 0; q < 4; q++) acc[i][j][q] = 0.f;

    // chunk -> global pointers
    auto srcA = [&](int c) -> const uint4* {
        int s = c / CHPS, kc = (c - s * CHPS) * BK;
        const __nv_bfloat16* Ag = (s == 1) ? Al : Ah;
        return (const uint4*)(Ag + (size_t)(m0 + ldrow) * GK + kc + ldhalf * 8);
    };
    auto srcB = [&](int c) -> const uint4* {
        int s = c / CHPS, kc = (c - s * CHPS) * BK;
        const __nv_bfloat16* Bg = (s == 2) ? Bl : Bh;
        return (const uint4*)(Bg + (size_t)(n0 + ldrow) * GK + kc + ldhalf * 8);
    };
    const uint32_t stoff = (uint32_t)ldrow * APAD + (uint32_t)ldhalf * 8;

    // preload chunk 0
    {
        uint4 va = *srcA(0);
        uint4 vb = *srcB(0);
        *(uint4*)&As[0][stoff] = va;
        *(uint4*)&Bs[0][stoff] = vb;
    }
    __syncthreads();

    for (int c = 0; c < NCHUNK; c++) {
        uint4 va, vb;
        const bool more = (c + 1 < NCHUNK);
        if (more) {
            va = *srcA(c + 1);
            vb = *srcB(c + 1);
        }
        const int buf = c & 1;
        const __nv_bfloat16* Ab = As[buf];
        const __nv_bfloat16* Bb = Bs[buf];

        uint32_t bfrag[4][2];
#pragma unroll
        for (int j = 0; j < 4; j++) {
            int rb = (wn * 32 + j * 8 + g) * APAD + tg * 2;
            bfrag[j][0] = *(const uint32_t*)&Bb[rb];
            bfrag[j][1] = *(const uint32_t*)&Bb[rb + 8];
        }
#pragma unroll
        for (int i = 0; i < 4; i++) {
            int ra0 = (wm * 64 + i * 16 + g) * APAD + tg * 2;
            int ra1 = ra0 + 8 * APAD;
            uint32_t a0 = *(const uint32_t*)&As[buf][ra0];
            uint32_t a1 = *(const uint32_t*)&As[buf][ra1];
            uint32_t a2 = *(const uint32_t*)&As[buf][ra0 + 8];
            uint32_t a3 = *(const uint32_t*)&As[buf][ra1 + 8];
#pragma unroll
            for (int j = 0; j < 4; j++)
                mma_bf16(acc[i][j], a0, a1, a2, a3, bfrag[j][0], bfrag[j][1]);
        }
        if (more) {
            *(uint4*)&As[buf ^ 1][stoff] = va;
            *(uint4*)&Bs[buf ^ 1][stoff] = vb;
        }
        __syncthreads();
    }

    // epilogue
#pragma unroll
    for (int i = 0; i < 4; i++) {
        int r0 = m0 + wm * 64 + i * 16 + g;
#pragma unroll
        for (int j = 0; j < 4; j++) {
            int cc = n0 + wn * 32 + j * 8 + tg * 2;
            float bx = 0.f, by = 0.f;
            if (bias) { bx = bias[cc]; by = bias[cc + 1]; }
            float2 v0 = { acc[i][j][0] + bx, acc[i][j][1] + by };
            float2 v1 = { acc[i][j][2] + bx, acc[i][j][3] + by };
            *(float2*)(C + (size_t)r0 * ldc + cc)       = v0;
            *(float2*)(C + (size_t)(r0 + 8) * ldc + cc) = v1;
        }
    }
}

// ---------------- per-row symmetric int8 quant of q and k ----------------
__global__ __launch_bounds__(256) void quant_qk_kernel()
{
    int warp = threadIdx.x >> 5, lane = threadIdx.x & 31;
    int row = blockIdx.x * 8 + warp;
    int t  = row >> 16;
    int rr = row & 65535;
    int bh = rr >> 11;
    int n  = rr & 2047;
    int b = bh >> 4, h = bh & 15;
    const float* src = g_qkv + (size_t)(b * NTOK + n) * K3 + t * CDIM + h * HD;

    float x0 = src[lane];
    float x1 = src[lane + 32];
    float x2 = (lane < 8) ? src[lane + 64] : 0.f;
    float amax = fmaxf(fabsf(x0), fmaxf(fabsf(x1), fabsf(x2)));
#pragma unroll
    for (int s = 16; s; s >>= 1) amax = fmaxf(amax, __shfl_xor_sync(0xffffffffu, amax, s));
    float scale = fmaxf(amax, 1e-8f) / 127.0f;

    signed char* dst = (t ? g_k8 : g_q8) + (size_t)(bh * NTOK + n) * QK_PAD;
    int q0 = min(127, max(-128, (int)rintf(__fdiv_rn(x0, scale))));
    int q1 = min(127, max(-128, (int)rintf(__fdiv_rn(x1, scale))));
    dst[lane]      = (signed char)q0;
    dst[lane + 32] = (signed char)q1;
    if (lane < 8) {
        int q2 = min(127, max(-128, (int)rintf(__fdiv_rn(x2, scale))));
        dst[lane + 64] = (signed char)q2;
    } else if (lane < 16) {
        dst[lane + 64] = 0;
    }
    if (lane == 0) (t ? g_ks : g_qs)[bh * NTOK + n] = scale;
}

// ---------------- per-channel int8 quant of v (over tokens, transposed) ----------------
__global__ __launch_bounds__(256) void quant_v_kernel()
{
    int col = blockIdx.x;
    int bh = col / HD, d = col % HD;
    int b = bh >> 4, h = bh & 15;
    const float* base = g_qkv + (size_t)b * NTOK * K3 + 2 * CDIM + h * HD + d;

    float vals[8];
    float amax = 0.f;
#pragma unroll
    for (int i = 0; i < 8; i++) {
        vals[i] = base[(size_t)(threadIdx.x + 256 * i) * K3];
        amax = fmaxf(amax, fabsf(vals[i]));
    }
    __shared__ float red[256];
    red[threadIdx.x] = amax;
    __syncthreads();
    for (int s = 128; s >= 1; s >>= 1) {
        if (threadIdx.x < s) red[threadIdx.x] = fmaxf(red[threadIdx.x], red[threadIdx.x + s]);
        __syncthreads();
    }
    float scale = fmaxf(red[0], 1e-8f) / 127.0f;

    signed char* dst = g_v8 + (size_t)(bh * HD + d) * NTOK;
#pragma unroll
    for (int i = 0; i < 8; i++) {
        int m = threadIdx.x + 256 * i;
        int q = min(127, max(-128, (int)rintf(__fdiv_rn(vals[i], scale))));
        dst[m] = (signed char)q;
    }
    if (threadIdx.x == 0) g_vs[bh * HD + d] = scale;
}

// ---------------- int8 QK^T logits GEMM (dp4a), 128x128 tile, 8x8/thread ----------------
__global__ __launch_bounds__(256) void logits_kernel()
{
    int bh   = blockIdx.z;
    int row0 = blockIdx.y * 128;
    int col0 = blockIdx.x * 128;
    __shared__ int qa[20][128];   // w-major
    __shared__ int kb[20][128];

    int tid = threadIdx.x;
    const int* qbase = (const int*)(g_q8 + (size_t)(bh * NTOK + row0) * QK_PAD);
    const int* kbase = (const int*)(g_k8 + (size_t)(bh * NTOK + col0) * QK_PAD);
    for (int idx = tid; idx < 128 * 20; idx += 256) {
        int rr = idx / 20, w = idx - rr * 20;
        qa[w][rr] = qbase[idx];
        kb[w][rr] = kbase[idx];
    }
    __syncthreads();

    int tx = tid & 15, ty = tid >> 4;
    int acc[8][8] = {};
#pragma unroll
    for (int w = 0; w < 20; w++) {
        int4 a0 = *(const int4*)&qa[w][ty * 8];
        int4 a1 = *(const int4*)&qa[w][ty * 8 + 4];
        int4 b0 = *(const int4*)&kb[w][tx * 8];
        int4 b1 = *(const int4*)&kb[w][tx * 8 + 4];
        int ar[8] = {a0.x, a0.y, a0.z, a0.w, a1.x, a1.y, a1.z, a1.w};
        int br[8] = {b0.x, b0.y, b0.z, b0.w, b1.x, b1.y, b1.z, b1.w};
#pragma unroll
        for (int i = 0; i < 8; i++)
#pragma unroll
            for (int j = 0; j < 8; j++)
                acc[i][j] = __dp4a(ar[i], br[j], acc[i][j]);
    }

    float ksv[8];
#pragma unroll
    for (int j = 0; j < 8; j++) ksv[j] = g_ks[bh * NTOK + col0 + tx * 8 + j];
#pragma unroll
    for (int i = 0; i < 8; i++) {
        int rr = row0 + ty * 8 + i;
        float qs = g_qs[bh * NTOK + rr] * ATT_SCALE;
        float* outp = g_logits + ((size_t)bh * NTOK + rr) * NTOK + col0 + tx * 8;
#pragma unroll
        for (int j = 0; j < 8; j += 4) {
            float4 v;
            v.x = (float)acc[i][j + 0] * qs * ksv[j + 0];
            v.y = (float)acc[i][j + 1] * qs * ksv[j + 1];
            v.z = (float)acc[i][j + 2] * qs * ksv[j + 2];
            v.w = (float)acc[i][j + 3] * qs * ksv[j + 3];
            *(float4*)(outp + j) = v;
        }
    }
}

// ---------------- softmax + unsigned 8-bit quant per row ----------------
__global__ __launch_bounds__(256) void softmax_kernel()
{
    size_t rowbase = (size_t)blockIdx.x * NTOK;
    const float* lrow = g_logits + rowbase;
    int tid = threadIdx.x;

    float l[8];
    float m = -1e30f;
#pragma unroll
    for (int i = 0; i < 8; i++) {
        l[i] = lrow[tid + 256 * i];
        m = fmaxf(m, l[i]);
    }
    __shared__ float red[256];
    red[tid] = m;
    __syncthreads();
    for (int s = 128; s >= 1; s >>= 1) {
        if (tid < s) red[tid] = fmaxf(red[tid], red[tid + s]);
        __syncthreads();
    }
    m = red[0];
    __syncthreads();

    float e[8];
    float z = 0.f;
#pragma unroll
    for (int i = 0; i < 8; i++) {
        e[i] = expf(l[i] - m);
        z += e[i];
    }
    red[tid] = z;
    __syncthreads();
    for (int s = 128; s >= 1; s >>= 1) {
        if (tid < s) red[tid] += red[tid + s];
        __syncthreads();
    }
    z = red[0];

    unsigned char* prow = g_p8 + rowbase;
#pragma unroll
    for (int i = 0; i < 8; i++) {
        int p = (int)rintf(255.0f * e[i]);
        p = min(255, max(0, p));
        prow[tid + 256 * i] = (unsigned char)p;
    }
    if (tid == 0) g_rowfac[blockIdx.x] = __fdiv_rn(1.0f, z) / 255.0f;
}

// ---------------- PV GEMM: u8 x s8 dp4a -> ctx in split bf16 ----------------
__global__ __launch_bounds__(288) void pv_kernel()
{
    int bh = blockIdx.y;
    int b = bh >> 4, hh = bh & 15;
    int row0 = blockIdx.x * 64;
    int lin = threadIdx.y * 72 + threadIdx.x;
    int d = threadIdx.x;

    __shared__ int pS[64][68];
    __shared__ int vS[72][68];

    const int* pbase = (const int*)(g_p8 + ((size_t)bh * NTOK + row0) * NTOK);
    const int* vbase = (const int*)(g_v8 + (size_t)bh * HD * NTOK);

    int acc[16] = {};

    for (int mc = 0; mc < 8; mc++) {
        __syncthreads();
        for (int idx = lin; idx < 64 * 64; idx += 288) {
            int rr = idx >> 6, w = idx & 63;
            pS[rr][w] = pbase[rr * 512 + mc * 64 + w];
        }
        for (int idx = lin; idx < 72 * 64; idx += 288) {
            int rr = idx >> 6, w = idx & 63;
            vS[rr][w] = vbase[rr * 512 + mc * 64 + w];
        }
        __syncthreads();
#pragma unroll
        for (int gg = 0; gg < 16; gg++) {
            int4 vv = *(const int4*)&vS[d][gg * 4];
#pragma unroll
            for (int rr = 0; rr < 16; rr++) {
                int4 pp = *(const int4*)&pS[threadIdx.y + 4 * rr][gg * 4];
                acc[rr] = dp4a_us((unsigned)pp.x, vv.x, acc[rr]);
                acc[rr] = dp4a_us((unsigned)pp.y, vv.y, acc[rr]);
                acc[rr] = dp4a_us((unsigned)pp.z, vv.z, acc[rr]);
                acc[rr] = dp4a_us((unsigned)pp.w, vv.w, acc[rr]);
            }
        }
    }

    float vsd = g_vs[bh * HD + d];
#pragma unroll
    for (int rr = 0; rr < 16; rr++) {
        int n = row0 + threadIdx.y + 4 * rr;
        float val = (float)acc[rr] * g_rowfac[bh * NTOK + n] * vsd;
        size_t idx = (size_t)(b * NTOK + n) * CDIM + hh * HD + d;
        __nv_bfloat16 vh = __float2bfloat16_rn(val);
        g_ctx_hi[idx] = vh;
        g_ctx_lo[idx] = __float2bfloat16_rn(val - __bfloat162float(vh));
    }
}

// ---------------- launch ----------------
extern "C" void kernel_launch(void* const* d_in, const int* in_sizes, int n_in,
                              void* d_out, int out_size)
{
    const float* x      = (const float*)d_in[0];
    const float* w_qkv  = (const float*)d_in[1];
    const float* w_proj = (const float*)d_in[2];
    const float* b_proj = (const float*)d_in[3];
    float* out = (float*)d_out;
    (void)in_sizes; (void)n_in; (void)out_size;

    void *p_qkv = nullptr;
    void *p_xh = nullptr, *p_xl = nullptr, *p_wqh = nullptr, *p_wql = nullptr;
    void *p_wph = nullptr, *p_wpl = nullptr, *p_cxh = nullptr, *p_cxl = nullptr;
    cudaGetSymbolAddress(&p_qkv, g_qkv);
    cudaGetSymbolAddress(&p_xh, g_x_hi);   cudaGetSymbolAddress(&p_xl, g_x_lo);
    cudaGetSymbolAddress(&p_wqh, g_wq_hi); cudaGetSymbolAddress(&p_wql, g_wq_lo);
    cudaGetSymbolAddress(&p_wph, g_wp_hi); cudaGetSymbolAddress(&p_wpl, g_wp_lo);
    cudaGetSymbolAddress(&p_cxh, g_ctx_hi); cudaGetSymbolAddress(&p_cxl, g_ctx_lo);

    // 0) split fp32 operands into bf16 hi/lo
    {
        int nx = MROWS * CDIM, nq = K3 * CDIM, np = CDIM * CDIM;
        split_kernel<<<(nx + 255) / 256, 256>>>(x, (__nv_bfloat16*)p_xh, (__nv_bfloat16*)p_xl, nx);
        split_kernel<<<(nq + 255) / 256, 256>>>(w_qkv, (__nv_bfloat16*)p_wqh, (__nv_bfloat16*)p_wql, nq);
        split_kernel<<<(np + 255) / 256, 256>>>(w_proj, (__nv_bfloat16*)p_wph, (__nv_bfloat16*)p_wpl, np);
    }

    // 1) QKV projection (HMMA bf16x3): [4096,3456]
    hmma_gemm_bf16x3<<<dim3(K3 / 128, MROWS / 128), 256>>>(
        (const __nv_bfloat16*)p_xh, (const __nv_bfloat16*)p_xl,
        (const __nv_bfloat16*)p_wqh, (const __nv_bfloat16*)p_wql,
        nullptr, (float*)p_qkv, K3);

    // 2) quantize q,k per row; v per channel
    quant_qk_kernel<<<2 * BH * NTOK / 8, 256>>>();
    quant_v_kernel<<<BH * HD, 256>>>();

    // 3) int8 logits GEMM
    logits_kernel<<<dim3(NTOK / 128, NTOK / 128, BH), 256>>>();

    // 4) softmax + u8 quant
    softmax_kernel<<<BH * NTOK, 256>>>();

    // 5) PV int GEMM -> ctx (split bf16)
    pv_kernel<<<dim3(NTOK / 64, BH), dim3(72, 4)>>>();

    // 6) output projection + bias (HMMA bf16x3)
    hmma_gemm_bf16x3<<<dim3(CDIM / 128, MROWS / 128), 256>>>(
        (const __nv_bfloat16*)p_cxh, (const __nv_bfloat16*)p_cxl,
        (const __nv_bfloat16*)p_wph, (const __nv_bfloat16*)p_wpl,
        b_proj, out, CDIM);
}

// round 4
// speedup vs baseline: 1.3055x; 1.1088x over previous
#include <cuda_runtime.h>
#include <cuda_bf16.h>
#include <cstdint>
#include <cstddef>

#define BATCH 2
#define NTOK 2048
#define CDIM 1152
#define HEADS 16
#define HD 72
#define BH (BATCH*HEADS)      /* 32   */
#define MROWS (BATCH*NTOK)    /* 4096 */
#define K3 (3*CDIM)           /* 3456 */
#define QK_PAD 80
#define ATT_SCALE 0.11785113019775793f  /* 72^-0.5 */

#define GK CDIM               /* K of both big GEMMs (per segment) */
#define BK 32                 /* K per smem chunk */
#define CHPS (GK/BK)          /* 36 */
#define NCHUNK (3*CHPS)       /* 108: hi*hi, lo*hi, hi*lo */
#define SMST 40               /* smem row stride in bf16 (80 B) */

// ---------------- scratch (static device memory) ----------------
__device__ float g_qkv[(size_t)MROWS * K3];
__device__ __align__(16) signed char g_q8[(size_t)BH * NTOK * QK_PAD];
__device__ __align__(16) signed char g_k8[(size_t)BH * NTOK * QK_PAD];
__device__ float g_qs[BH * NTOK];
__device__ float g_ks[BH * NTOK];
__device__ __align__(16) signed char g_v8[(size_t)BH * HD * NTOK];   // [bh][d][m]
__device__ float g_vs[BH * HD];
__device__ float g_logits[(size_t)BH * NTOK * NTOK];
__device__ __align__(16) unsigned char g_p8[(size_t)BH * NTOK * NTOK];
__device__ float g_rowfac[BH * NTOK];

// bf16 split operands
__device__ __align__(16) __nv_bfloat16 g_x_hi[(size_t)MROWS * CDIM];
__device__ __align__(16) __nv_bfloat16 g_x_lo[(size_t)MROWS * CDIM];
__device__ __align__(16) __nv_bfloat16 g_wq_hi[(size_t)K3 * CDIM];
__device__ __align__(16) __nv_bfloat16 g_wq_lo[(size_t)K3 * CDIM];
__device__ __align__(16) __nv_bfloat16 g_wp_hi[(size_t)CDIM * CDIM];
__device__ __align__(16) __nv_bfloat16 g_wp_lo[(size_t)CDIM * CDIM];
__device__ __align__(16) __nv_bfloat16 g_ctx_hi[(size_t)MROWS * CDIM];
__device__ __align__(16) __nv_bfloat16 g_ctx_lo[(size_t)MROWS * CDIM];

__device__ __forceinline__ int dp4a_us(unsigned int a, int b, int c) {
    int d;
    asm("dp4a.u32.s32 %0, %1, %2, %3;" : "=r"(d) : "r"(a), "r"(b), "r"(c));
    return d;
}

__device__ __forceinline__ uint32_t smem_u32(const void* p) {
    uint32_t a;
    asm("{ .reg .u64 t; cvta.to.shared.u64 t, %1; cvt.u32.u64 %0, t; }" : "=r"(a) : "l"(p));
    return a;
}

__device__ __forceinline__ void mma_bf16(float* c, uint32_t a0, uint32_t a1,
                                         uint32_t a2, uint32_t a3,
                                         uint32_t b0, uint32_t b1) {
    asm volatile(
        "mma.sync.aligned.m16n8k16.row.col.f32.bf16.bf16.f32 "
        "{%0,%1,%2,%3}, {%4,%5,%6,%7}, {%8,%9}, {%0,%1,%2,%3};"
        : "+f"(c[0]), "+f"(c[1]), "+f"(c[2]), "+f"(c[3])
        : "r"(a0), "r"(a1), "r"(a2), "r"(a3), "r"(b0), "r"(b1));
}

__device__ __forceinline__ void ldsm4(uint32_t& r0, uint32_t& r1, uint32_t& r2,
                                      uint32_t& r3, uint32_t addr) {
    asm volatile("ldmatrix.sync.aligned.m8n8.x4.shared.b16 {%0,%1,%2,%3}, [%4];"
                 : "=r"(r0), "=r"(r1), "=r"(r2), "=r"(r3) : "r"(addr));
}

__device__ __forceinline__ void cp16(uint32_t dst, const void* src) {
    asm volatile("cp.async.cg.shared.global [%0], [%1], 16;" :: "r"(dst), "l"(src));
}

// ---------------- split fp32 -> bf16 hi + lo ----------------
__global__ __launch_bounds__(256) void split_kernel(const float* __restrict__ s,
                                                    __nv_bfloat16* __restrict__ hi,
                                                    __nv_bfloat16* __restrict__ lo, int n)
{
    int i = blockIdx.x * 256 + threadIdx.x;
    if (i < n) {
        float v = s[i];
        __nv_bfloat16 h = __float2bfloat16_rn(v);
        hi[i] = h;
        lo[i] = __float2bfloat16_rn(v - __bfloat162float(h));
    }
}

// ---------------- HMMA bf16x3 GEMM: C[M,N] = A[M,GK] @ B[N,GK]^T (+bias) ----------------
// 128x128 tile, 256 threads (8 warps as 2x4), warp tile 64x32 via m16n8k16.
// ldmatrix.x4 fragment loads + cp.async double-buffered staging, BK=32.
__global__ __launch_bounds__(256, 2) void hmma_gemm_bf16x3(
    const __nv_bfloat16* __restrict__ Ah, const __nv_bfloat16* __restrict__ Al,
    const __nv_bfloat16* __restrict__ Bh, const __nv_bfloat16* __restrict__ Bl,
    const float* __restrict__ bias, float* __restrict__ C, int ldc)
{
    __shared__ __nv_bfloat16 As[2][128 * SMST];
    __shared__ __nv_bfloat16 Bs[2][128 * SMST];

    const int tid = threadIdx.x;
    const int wid = tid >> 5;
    const int lane = tid & 31;
    const int g  = lane >> 2;     // 0..7
    const int tg = lane & 3;      // 0..3
    const int wm = wid >> 2;      // 0..1 -> 64-row slab
    const int wn = wid & 3;       // 0..3 -> 32-col slab
    const int m0 = blockIdx.y * 128;
    const int n0 = blockIdx.x * 128;

    // staging: thread -> (row, 2 consecutive 16B units)
    const int sr = tid >> 1;              // 0..127
    const int su = (tid & 1) * 2;         // unit 0/1 or 2/3 (16B units along k)

    const uint32_t sA0 = smem_u32(&As[0][0]);
    const uint32_t sB0 = smem_u32(&Bs[0][0]);
    const uint32_t BUFB = 128 * SMST * 2; // bytes per buffer
    const uint32_t stb = (uint32_t)sr * (SMST * 2) + (uint32_t)su * 16;

    // ldmatrix lane addressing
    const int lq = lane >> 3, lr = lane & 7;
    // A: matrix q -> row + (q&1)*8, kbyte + (q>>1)*16
    const uint32_t a_off = (uint32_t)((wm * 64 + (lq & 1) * 8 + lr) * SMST * 2 + (lq >> 1) * 16);
    // B: matrix q -> row + (q>>1)*8, kbyte + (q&1)*16
    const uint32_t b_off = (uint32_t)((wn * 32 + (lq >> 1) * 8 + lr) * SMST * 2 + (lq & 1) * 16);

    float acc[4][4][4];
#pragma unroll
    for (int i = 0; i < 4; i++)
#pragma unroll
        for (int j = 0; j < 4; j++)
#pragma unroll
            for (int q = 0; q < 4; q++) acc[i][j][q] = 0.f;

    auto issue_loads = [&](int c, int buf) {
        int s = c / CHPS, kc = (c - s * CHPS) * BK;
        const __nv_bfloat16* Ag = (s == 1) ? Al : Ah;
        const __nv_bfloat16* Bg = (s == 2) ? Bl : Bh;
        const char* ga = (const char*)(Ag + (size_t)(m0 + sr) * GK + kc) + su * 16;
        const char* gb = (const char*)(Bg + (size_t)(n0 + sr) * GK + kc) + su * 16;
        uint32_t da = sA0 + (uint32_t)buf * BUFB + stb;
        uint32_t db = sB0 + (uint32_t)buf * BUFB + stb;
        cp16(da, ga);            cp16(da + 16, ga + 16);
        cp16(db, gb);            cp16(db + 16, gb + 16);
    };

    issue_loads(0, 0);
    asm volatile("cp.async.commit_group;" ::: "memory");

    for (int c = 0; c < NCHUNK; c++) {
        const int buf = c & 1;
        if (c + 1 < NCHUNK) issue_loads(c + 1, buf ^ 1);
        asm volatile("cp.async.commit_group;" ::: "memory");
        asm volatile("cp.async.wait_group 1;" ::: "memory");
        __syncthreads();

        const uint32_t aB = sA0 + (uint32_t)buf * BUFB + a_off;
        const uint32_t bB = sB0 + (uint32_t)buf * BUFB + b_off;
#pragma unroll
        for (int kk = 0; kk < 2; kk++) {
            uint32_t bf[4][2];
#pragma unroll
            for (int jj = 0; jj < 2; jj++) {
                uint32_t t0, t1, t2, t3;
                ldsm4(t0, t1, t2, t3, bB + (uint32_t)(jj * 16 * SMST * 2 + kk * 32));
                bf[2 * jj][0] = t0;     bf[2 * jj][1] = t1;
                bf[2 * jj + 1][0] = t2; bf[2 * jj + 1][1] = t3;
            }
#pragma unroll
            for (int i = 0; i < 4; i++) {
                uint32_t a0, a1, a2, a3;
                ldsm4(a0, a1, a2, a3, aB + (uint32_t)(i * 16 * SMST * 2 + kk * 32));
#pragma unroll
                for (int j = 0; j < 4; j++)
                    mma_bf16(acc[i][j], a0, a1, a2, a3, bf[j][0], bf[j][1]);
            }
        }
        __syncthreads();
    }

    // epilogue
#pragma unroll
    for (int i = 0; i < 4; i++) {
        int r0 = m0 + wm * 64 + i * 16 + g;
#pragma unroll
        for (int j = 0; j < 4; j++) {
            int cc = n0 + wn * 32 + j * 8 + tg * 2;
            float bx = 0.f, by = 0.f;
            if (bias) { bx = bias[cc]; by = bias[cc + 1]; }
            float2 v0 = { acc[i][j][0] + bx, acc[i][j][1] + by };
            float2 v1 = { acc[i][j][2] + bx, acc[i][j][3] + by };
            *(float2*)(C + (size_t)r0 * ldc + cc)       = v0;
            *(float2*)(C + (size_t)(r0 + 8) * ldc + cc) = v1;
        }
    }
}

// ---------------- per-row symmetric int8 quant of q and k ----------------
__global__ __launch_bounds__(256) void quant_qk_kernel()
{
    int warp = threadIdx.x >> 5, lane = threadIdx.x & 31;
    int row = blockIdx.x * 8 + warp;
    int t  = row >> 16;
    int rr = row & 65535;
    int bh = rr >> 11;
    int n  = rr & 2047;
    int b = bh >> 4, h = bh & 15;
    const float* src = g_qkv + (size_t)(b * NTOK + n) * K3 + t * CDIM + h * HD;

    float x0 = src[lane];
    float x1 = src[lane + 32];
    float x2 = (lane < 8) ? src[lane + 64] : 0.f;
    float amax = fmaxf(fabsf(x0), fmaxf(fabsf(x1), fabsf(x2)));
#pragma unroll
    for (int s = 16; s; s >>= 1) amax = fmaxf(amax, __shfl_xor_sync(0xffffffffu, amax, s));
    float scale = fmaxf(amax, 1e-8f) / 127.0f;

    signed char* dst = (t ? g_k8 : g_q8) + (size_t)(bh * NTOK + n) * QK_PAD;
    int q0 = min(127, max(-128, (int)rintf(__fdiv_rn(x0, scale))));
    int q1 = min(127, max(-128, (int)rintf(__fdiv_rn(x1, scale))));
    dst[lane]      = (signed char)q0;
    dst[lane + 32] = (signed char)q1;
    if (lane < 8) {
        int q2 = min(127, max(-128, (int)rintf(__fdiv_rn(x2, scale))));
        dst[lane + 64] = (signed char)q2;
    } else if (lane < 16) {
        dst[lane + 64] = 0;
    }
    if (lane == 0) (t ? g_ks : g_qs)[bh * NTOK + n] = scale;
}

// ---------------- per-channel int8 quant of v (over tokens, transposed) ----------------
__global__ __launch_bounds__(256) void quant_v_kernel()
{
    int col = blockIdx.x;
    int bh = col / HD, d = col % HD;
    int b = bh >> 4, h = bh & 15;
    const float* base = g_qkv + (size_t)b * NTOK * K3 + 2 * CDIM + h * HD + d;

    float vals[8];
    float amax = 0.f;
#pragma unroll
    for (int i = 0; i < 8; i++) {
        vals[i] = base[(size_t)(threadIdx.x + 256 * i) * K3];
        amax = fmaxf(amax, fabsf(vals[i]));
    }
    __shared__ float red[256];
    red[threadIdx.x] = amax;
    __syncthreads();
    for (int s = 128; s >= 1; s >>= 1) {
        if (threadIdx.x < s) red[threadIdx.x] = fmaxf(red[threadIdx.x], red[threadIdx.x + s]);
        __syncthreads();
    }
    float scale = fmaxf(red[0], 1e-8f) / 127.0f;

    signed char* dst = g_v8 + (size_t)(bh * HD + d) * NTOK;
#pragma unroll
    for (int i = 0; i < 8; i++) {
        int m = threadIdx.x + 256 * i;
        int q = min(127, max(-128, (int)rintf(__fdiv_rn(vals[i], scale))));
        dst[m] = (signed char)q;
    }
    if (threadIdx.x == 0) g_vs[bh * HD + d] = scale;
}

// ---------------- int8 QK^T logits GEMM (dp4a), 128x128 tile, 8x8/thread ----------------
__global__ __launch_bounds__(256) void logits_kernel()
{
    int bh   = blockIdx.z;
    int row0 = blockIdx.y * 128;
    int col0 = blockIdx.x * 128;
    __shared__ int qa[20][128];   // w-major
    __shared__ int kb[20][128];

    int tid = threadIdx.x;
    const int* qbase = (const int*)(g_q8 + (size_t)(bh * NTOK + row0) * QK_PAD);
    const int* kbase = (const int*)(g_k8 + (size_t)(bh * NTOK + col0) * QK_PAD);
    for (int idx = tid; idx < 128 * 20; idx += 256) {
        int rr = idx / 20, w = idx - rr * 20;
        qa[w][rr] = qbase[idx];
        kb[w][rr] = kbase[idx];
    }
    __syncthreads();

    int tx = tid & 15, ty = tid >> 4;
    int acc[8][8] = {};
#pragma unroll
    for (int w = 0; w < 20; w++) {
        int4 a0 = *(const int4*)&qa[w][ty * 8];
        int4 a1 = *(const int4*)&qa[w][ty * 8 + 4];
        int4 b0 = *(const int4*)&kb[w][tx * 8];
        int4 b1 = *(const int4*)&kb[w][tx * 8 + 4];
        int ar[8] = {a0.x, a0.y, a0.z, a0.w, a1.x, a1.y, a1.z, a1.w};
        int br[8] = {b0.x, b0.y, b0.z, b0.w, b1.x, b1.y, b1.z, b1.w};
#pragma unroll
        for (int i = 0; i < 8; i++)
#pragma unroll
            for (int j = 0; j < 8; j++)
                acc[i][j] = __dp4a(ar[i], br[j], acc[i][j]);
    }

    float ksv[8];
#pragma unroll
    for (int j = 0; j < 8; j++) ksv[j] = g_ks[bh * NTOK + col0 + tx * 8 + j];
#pragma unroll
    for (int i = 0; i < 8; i++) {
        int rr = row0 + ty * 8 + i;
        float qs = g_qs[bh * NTOK + rr] * ATT_SCALE;
        float* outp = g_logits + ((size_t)bh * NTOK + rr) * NTOK + col0 + tx * 8;
#pragma unroll
        for (int j = 0; j < 8; j += 4) {
            float4 v;
            v.x = (float)acc[i][j + 0] * qs * ksv[j + 0];
            v.y = (float)acc[i][j + 1] * qs * ksv[j + 1];
            v.z = (float)acc[i][j + 2] * qs * ksv[j + 2];
            v.w = (float)acc[i][j + 3] * qs * ksv[j + 3];
            *(float4*)(outp + j) = v;
        }
    }
}

// ---------------- softmax + unsigned 8-bit quant per row ----------------
__global__ __launch_bounds__(256) void softmax_kernel()
{
    size_t rowbase = (size_t)blockIdx.x * NTOK;
    const float* lrow = g_logits + rowbase;
    int tid = threadIdx.x;

    float l[8];
    float m = -1e30f;
#pragma unroll
    for (int i = 0; i < 8; i++) {
        l[i] = lrow[tid + 256 * i];
        m = fmaxf(m, l[i]);
    }
    __shared__ float red[256];
    red[tid] = m;
    __syncthreads();
    for (int s = 128; s >= 1; s >>= 1) {
        if (tid < s) red[tid] = fmaxf(red[tid], red[tid + s]);
        __syncthreads();
    }
    m = red[0];
    __syncthreads();

    float e[8];
    float z = 0.f;
#pragma unroll
    for (int i = 0; i < 8; i++) {
        e[i] = expf(l[i] - m);
        z += e[i];
    }
    red[tid] = z;
    __syncthreads();
    for (int s = 128; s >= 1; s >>= 1) {
        if (tid < s) red[tid] += red[tid + s];
        __syncthreads();
    }
    z = red[0];

    unsigned char* prow = g_p8 + rowbase;
#pragma unroll
    for (int i = 0; i < 8; i++) {
        int p = (int)rintf(255.0f * e[i]);
        p = min(255, max(0, p));
        prow[tid + 256 * i] = (unsigned char)p;
    }
    if (tid == 0) g_rowfac[blockIdx.x] = __fdiv_rn(1.0f, z) / 255.0f;
}

// ---------------- PV GEMM: u8 x s8 dp4a -> ctx in split bf16 ----------------
__global__ __launch_bounds__(288) void pv_kernel()
{
    int bh = blockIdx.y;
    int b = bh >> 4, hh = bh & 15;
    int row0 = blockIdx.x * 64;
    int lin = threadIdx.y * 72 + threadIdx.x;
    int d = threadIdx.x;

    __shared__ int pS[64][68];
    __shared__ int vS[72][68];

    const int* pbase = (const int*)(g_p8 + ((size_t)bh * NTOK + row0) * NTOK);
    const int* vbase = (const int*)(g_v8 + (size_t)bh * HD * NTOK);

    int acc[16] = {};

    for (int mc = 0; mc < 8; mc++) {
        __syncthreads();
        for (int idx = lin; idx < 64 * 64; idx += 288) {
            int rr = idx >> 6, w = idx & 63;
            pS[rr][w] = pbase[rr * 512 + mc * 64 + w];
        }
        for (int idx = lin; idx < 72 * 64; idx += 288) {
            int rr = idx >> 6, w = idx & 63;
            vS[rr][w] = vbase[rr * 512 + mc * 64 + w];
        }
        __syncthreads();
#pragma unroll
        for (int gg = 0; gg < 16; gg++) {
            int4 vv = *(const int4*)&vS[d][gg * 4];
#pragma unroll
            for (int rr = 0; rr < 16; rr++) {
                int4 pp = *(const int4*)&pS[threadIdx.y + 4 * rr][gg * 4];
                acc[rr] = dp4a_us((unsigned)pp.x, vv.x, acc[rr]);
                acc[rr] = dp4a_us((unsigned)pp.y, vv.y, acc[rr]);
                acc[rr] = dp4a_us((unsigned)pp.z, vv.z, acc[rr]);
                acc[rr] = dp4a_us((unsigned)pp.w, vv.w, acc[rr]);
            }
        }
    }

    float vsd = g_vs[bh * HD + d];
#pragma unroll
    for (int rr = 0; rr < 16; rr++) {
        int n = row0 + threadIdx.y + 4 * rr;
        float val = (float)acc[rr] * g_rowfac[bh * NTOK + n] * vsd;
        size_t idx = (size_t)(b * NTOK + n) * CDIM + hh * HD + d;
        __nv_bfloat16 vh = __float2bfloat16_rn(val);
        g_ctx_hi[idx] = vh;
        g_ctx_lo[idx] = __float2bfloat16_rn(val - __bfloat162float(vh));
    }
}

// ---------------- launch ----------------
extern "C" void kernel_launch(void* const* d_in, const int* in_sizes, int n_in,
                              void* d_out, int out_size)
{
    const float* x      = (const float*)d_in[0];
    const float* w_qkv  = (const float*)d_in[1];
    const float* w_proj = (const float*)d_in[2];
    const float* b_proj = (const float*)d_in[3];
    float* out = (float*)d_out;
    (void)in_sizes; (void)n_in; (void)out_size;

    void *p_qkv = nullptr;
    void *p_xh = nullptr, *p_xl = nullptr, *p_wqh = nullptr, *p_wql = nullptr;
    void *p_wph = nullptr, *p_wpl = nullptr, *p_cxh = nullptr, *p_cxl = nullptr;
    cudaGetSymbolAddress(&p_qkv, g_qkv);
    cudaGetSymbolAddress(&p_xh, g_x_hi);   cudaGetSymbolAddress(&p_xl, g_x_lo);
    cudaGetSymbolAddress(&p_wqh, g_wq_hi); cudaGetSymbolAddress(&p_wql, g_wq_lo);
    cudaGetSymbolAddress(&p_wph, g_wp_hi); cudaGetSymbolAddress(&p_wpl, g_wp_lo);
    cudaGetSymbolAddress(&p_cxh, g_ctx_hi); cudaGetSymbolAddress(&p_cxl, g_ctx_lo);

    // 0) split fp32 operands into bf16 hi/lo
    {
        int nx = MROWS * CDIM, nq = K3 * CDIM, np = CDIM * CDIM;
        split_kernel<<<(nx + 255) / 256, 256>>>(x, (__nv_bfloat16*)p_xh, (__nv_bfloat16*)p_xl, nx);
        split_kernel<<<(nq + 255) / 256, 256>>>(w_qkv, (__nv_bfloat16*)p_wqh, (__nv_bfloat16*)p_wql, nq);
        split_kernel<<<(np + 255) / 256, 256>>>(w_proj, (__nv_bfloat16*)p_wph, (__nv_bfloat16*)p_wpl, np);
    }

    // 1) QKV projection (HMMA bf16x3): [4096,3456]
    hmma_gemm_bf16x3<<<dim3(K3 / 128, MROWS / 128), 256>>>(
        (const __nv_bfloat16*)p_xh, (const __nv_bfloat16*)p_xl,
        (const __nv_bfloat16*)p_wqh, (const __nv_bfloat16*)p_wql,
        nullptr, (float*)p_qkv, K3);

    // 2) quantize q,k per row; v per channel
    quant_qk_kernel<<<2 * BH * NTOK / 8, 256>>>();
    quant_v_kernel<<<BH * HD, 256>>>();

    // 3) int8 logits GEMM
    logits_kernel<<<dim3(NTOK / 128, NTOK / 128, BH), 256>>>();

    // 4) softmax + u8 quant
    softmax_kernel<<<BH * NTOK, 256>>>();

    // 5) PV int GEMM -> ctx (split bf16)
    pv_kernel<<<dim3(NTOK / 64, BH), dim3(72, 4)>>>();

    // 6) output projection + bias (HMMA bf16x3)
    hmma_gemm_bf16x3<<<dim3(CDIM / 128, MROWS / 128), 256>>>(
        (const __nv_bfloat16*)p_cxh, (const __nv_bfloat16*)p_cxl,
        (const __nv_bfloat16*)p_wph, (const __nv_bfloat16*)p_wpl,
        b_proj, out, CDIM);
}

// round 6
// speedup vs baseline: 1.6371x; 1.2540x over previous
#include <cuda_runtime.h>
#include <cuda_bf16.h>
#include <cstdint>
#include <cstddef>

#define BATCH 2
#define NTOK 2048
#define CDIM 1152
#define HEADS 16
#define HD 72
#define BH (BATCH*HEADS)      /* 32   */
#define MROWS (BATCH*NTOK)    /* 4096 */
#define K3 (3*CDIM)           /* 3456 */
#define QK_PAD 96             /* padded bytes per q/k row (72 -> 96) */
#define QK_SST 112            /* smem row stride for q/k tiles */
#define ATT_SCALE 0.11785113019775793f  /* 72^-0.5 */

#define GK CDIM               /* K of both big GEMMs (per segment) */
#define BK 32                 /* K per smem chunk */
#define CHPS (GK/BK)          /* 36 */
#define NCHUNK (3*CHPS)       /* 108: hi*hi, lo*hi, hi*lo */
#define SMST 40               /* gemm smem row stride in bf16 (80 B) */
#define GS 4                  /* gemm pipeline stages */

// ---------------- scratch (static device memory) ----------------
__device__ float g_qkv[(size_t)MROWS * K3];
__device__ __align__(16) signed char g_q8[(size_t)BH * NTOK * QK_PAD];
__device__ __align__(16) signed char g_k8[(size_t)BH * NTOK * QK_PAD];
__device__ float g_qs[BH * NTOK];
__device__ float g_ks[BH * NTOK];
__device__ __align__(16) signed char g_v8[(size_t)BH * HD * NTOK];   // [bh][d][m]
__device__ float g_vs[BH * HD];
__device__ float g_logits[(size_t)BH * NTOK * NTOK];
__device__ __align__(16) unsigned char g_p8[(size_t)BH * NTOK * NTOK];
__device__ float g_rowfac[BH * NTOK];

// bf16 split operands
__device__ __align__(16) __nv_bfloat16 g_x_hi[(size_t)MROWS * CDIM];
__device__ __align__(16) __nv_bfloat16 g_x_lo[(size_t)MROWS * CDIM];
__device__ __align__(16) __nv_bfloat16 g_wq_hi[(size_t)K3 * CDIM];
__device__ __align__(16) __nv_bfloat16 g_wq_lo[(size_t)K3 * CDIM];
__device__ __align__(16) __nv_bfloat16 g_wp_hi[(size_t)CDIM * CDIM];
__device__ __align__(16) __nv_bfloat16 g_wp_lo[(size_t)CDIM * CDIM];
__device__ __align__(16) __nv_bfloat16 g_ctx_hi[(size_t)MROWS * CDIM];
__device__ __align__(16) __nv_bfloat16 g_ctx_lo[(size_t)MROWS * CDIM];

// ---------------- helpers ----------------
__device__ __forceinline__ uint32_t smem_u32(const void* p) {
    uint32_t a;
    asm("{ .reg .u64 t; cvta.to.shared.u64 t, %1; cvt.u32.u64 %0, t; }" : "=r"(a) : "l"(p));
    return a;
}
__device__ __forceinline__ uint32_t lds32(uint32_t addr) {
    uint32_t v;
    asm volatile("ld.shared.b32 %0, [%1];" : "=r"(v) : "r"(addr));
    return v;
}
__device__ __forceinline__ void mma_bf16(float* c, uint32_t a0, uint32_t a1,
                                         uint32_t a2, uint32_t a3,
                                         uint32_t b0, uint32_t b1) {
    asm volatile(
        "mma.sync.aligned.m16n8k16.row.col.f32.bf16.bf16.f32 "
        "{%0,%1,%2,%3}, {%4,%5,%6,%7}, {%8,%9}, {%0,%1,%2,%3};"
        : "+f"(c[0]), "+f"(c[1]), "+f"(c[2]), "+f"(c[3])
        : "r"(a0), "r"(a1), "r"(a2), "r"(a3), "r"(b0), "r"(b1));
}
__device__ __forceinline__ void mma_s8(int* c, uint32_t a0, uint32_t a1,
                                       uint32_t a2, uint32_t a3,
                                       uint32_t b0, uint32_t b1) {
    asm volatile(
        "mma.sync.aligned.m16n8k32.row.col.s32.s8.s8.s32 "
        "{%0,%1,%2,%3}, {%4,%5,%6,%7}, {%8,%9}, {%0,%1,%2,%3};"
        : "+r"(c[0]), "+r"(c[1]), "+r"(c[2]), "+r"(c[3])
        : "r"(a0), "r"(a1), "r"(a2), "r"(a3), "r"(b0), "r"(b1));
}
__device__ __forceinline__ void mma_u8s8(int* c, uint32_t a0, uint32_t a1,
                                         uint32_t a2, uint32_t a3,
                                         uint32_t b0, uint32_t b1) {
    asm volatile(
        "mma.sync.aligned.m16n8k32.row.col.s32.u8.s8.s32 "
        "{%0,%1,%2,%3}, {%4,%5,%6,%7}, {%8,%9}, {%0,%1,%2,%3};"
        : "+r"(c[0]), "+r"(c[1]), "+r"(c[2]), "+r"(c[3])
        : "r"(a0), "r"(a1), "r"(a2), "r"(a3), "r"(b0), "r"(b1));
}
__device__ __forceinline__ void ldsm4(uint32_t& r0, uint32_t& r1, uint32_t& r2,
                                      uint32_t& r3, uint32_t addr) {
    asm volatile("ldmatrix.sync.aligned.m8n8.x4.shared.b16 {%0,%1,%2,%3}, [%4];"
                 : "=r"(r0), "=r"(r1), "=r"(r2), "=r"(r3) : "r"(addr));
}
__device__ __forceinline__ void cp16(uint32_t dst, const void* src) {
    asm volatile("cp.async.cg.shared.global [%0], [%1], 16;" :: "r"(dst), "l"(src));
}

// ---------------- split fp32 -> bf16 hi + lo ----------------
__global__ __launch_bounds__(256) void split_kernel(const float* __restrict__ s,
                                                    __nv_bfloat16* __restrict__ hi,
                                                    __nv_bfloat16* __restrict__ lo, int n)
{
    int i = blockIdx.x * 256 + threadIdx.x;
    if (i < n) {
        float v = s[i];
        __nv_bfloat16 h = __float2bfloat16_rn(v);
        hi[i] = h;
        lo[i] = __float2bfloat16_rn(v - __bfloat162float(h));
    }
}

// ---------------- HMMA bf16x3 GEMM, 4-stage cp.async pipeline ----------------
__global__ __launch_bounds__(256, 2) void hmma_gemm_bf16x3(
    const __nv_bfloat16* __restrict__ Ah, const __nv_bfloat16* __restrict__ Al,
    const __nv_bfloat16* __restrict__ Bh, const __nv_bfloat16* __restrict__ Bl,
    const float* __restrict__ bias, float* __restrict__ C, int ldc)
{
    extern __shared__ char dynsm[];
    const uint32_t SB  = 128 * SMST * 2;   // bytes per A (or B) buffer
    const uint32_t STG = 2 * SB;           // bytes per stage

    const int tid = threadIdx.x;
    const int wid = tid >> 5;
    const int lane = tid & 31;
    const int g  = lane >> 2;
    const int tg = lane & 3;
    const int wm = wid >> 2;
    const int wn = wid & 3;
    const int m0 = blockIdx.y * 128;
    const int n0 = blockIdx.x * 128;

    const int sr = tid >> 1;
    const int su = (tid & 1) * 2;
    const uint32_t s0 = smem_u32(dynsm);
    const uint32_t stb = (uint32_t)sr * (SMST * 2) + (uint32_t)su * 16;

    const int lq = lane >> 3, lr = lane & 7;
    const uint32_t a_off = (uint32_t)((wm * 64 + (lq & 1) * 8 + lr) * SMST * 2 + (lq >> 1) * 16);
    const uint32_t b_off = (uint32_t)((wn * 32 + (lq >> 1) * 8 + lr) * SMST * 2 + (lq & 1) * 16);

    float acc[4][4][4];
#pragma unroll
    for (int i = 0; i < 4; i++)
#pragma unroll
        for (int j = 0; j < 4; j++)
#pragma unroll
            for (int q = 0; q < 4; q++) acc[i][j][q] = 0.f;

    auto issue_loads = [&](int c, int stg) {
        int s = c / CHPS, kc = (c - s * CHPS) * BK;
        const __nv_bfloat16* Ag = (s == 1) ? Al : Ah;
        const __nv_bfloat16* Bg = (s == 2) ? Bl : Bh;
        const char* ga = (const char*)(Ag + (size_t)(m0 + sr) * GK + kc) + su * 16;
        const char* gb = (const char*)(Bg + (size_t)(n0 + sr) * GK + kc) + su * 16;
        uint32_t da = s0 + (uint32_t)stg * STG + stb;
        uint32_t db = da + SB;
        cp16(da, ga);  cp16(da + 16, ga + 16);
        cp16(db, gb);  cp16(db + 16, gb + 16);
    };

#pragma unroll
    for (int s = 0; s < GS - 1; s++) {
        issue_loads(s, s);
        asm volatile("cp.async.commit_group;" ::: "memory");
    }

    for (int c = 0; c < NCHUNK; c++) {
        asm volatile("cp.async.wait_group %0;" :: "n"(GS - 2) : "memory");
        __syncthreads();
        if (c + GS - 1 < NCHUNK) issue_loads(c + GS - 1, (c + GS - 1) % GS);
        asm volatile("cp.async.commit_group;" ::: "memory");

        const uint32_t base = s0 + (uint32_t)(c % GS) * STG;
        const uint32_t aB = base + a_off;
        const uint32_t bB = base + SB + b_off;
#pragma unroll
        for (int kk = 0; kk < 2; kk++) {
            uint32_t bf[4][2];
#pragma unroll
            for (int jj = 0; jj < 2; jj++) {
                uint32_t t0, t1, t2, t3;
                ldsm4(t0, t1, t2, t3, bB + (uint32_t)(jj * 16 * SMST * 2 + kk * 32));
                bf[2 * jj][0] = t0;     bf[2 * jj][1] = t1;
                bf[2 * jj + 1][0] = t2; bf[2 * jj + 1][1] = t3;
            }
#pragma unroll
            for (int i = 0; i < 4; i++) {
                uint32_t a0, a1, a2, a3;
                ldsm4(a0, a1, a2, a3, aB + (uint32_t)(i * 16 * SMST * 2 + kk * 32));
#pragma unroll
                for (int j = 0; j < 4; j++)
                    mma_bf16(acc[i][j], a0, a1, a2, a3, bf[j][0], bf[j][1]);
            }
        }
    }

#pragma unroll
    for (int i = 0; i < 4; i++) {
        int r0 = m0 + wm * 64 + i * 16 + g;
#pragma unroll
        for (int j = 0; j < 4; j++) {
            int cc = n0 + wn * 32 + j * 8 + tg * 2;
            float bx = 0.f, by = 0.f;
            if (bias) { bx = bias[cc]; by = bias[cc + 1]; }
            float2 v0 = { acc[i][j][0] + bx, acc[i][j][1] + by };
            float2 v1 = { acc[i][j][2] + bx, acc[i][j][3] + by };
            *(float2*)(C + (size_t)r0 * ldc + cc)       = v0;
            *(float2*)(C + (size_t)(r0 + 8) * ldc + cc) = v1;
        }
    }
}

// ---------------- per-row symmetric int8 quant of q and k (96B padded rows) ----------------
__global__ __launch_bounds__(256) void quant_qk_kernel()
{
    int warp = threadIdx.x >> 5, lane = threadIdx.x & 31;
    int row = blockIdx.x * 8 + warp;
    int t  = row >> 16;
    int rr = row & 65535;
    int bh = rr >> 11;
    int n  = rr & 2047;
    int b = bh >> 4, h = bh & 15;
    const float* src = g_qkv + (size_t)(b * NTOK + n) * K3 + t * CDIM + h * HD;

    float x0 = src[lane];
    float x1 = src[lane + 32];
    float x2 = (lane < 8) ? src[lane + 64] : 0.f;
    float amax = fmaxf(fabsf(x0), fmaxf(fabsf(x1), fabsf(x2)));
#pragma unroll
    for (int s = 16; s; s >>= 1) amax = fmaxf(amax, __shfl_xor_sync(0xffffffffu, amax, s));
    float scale = fmaxf(amax, 1e-8f) / 127.0f;

    signed char* dst = (t ? g_k8 : g_q8) + (size_t)(bh * NTOK + n) * QK_PAD;
    int q0 = min(127, max(-128, (int)rintf(__fdiv_rn(x0, scale))));
    int q1 = min(127, max(-128, (int)rintf(__fdiv_rn(x1, scale))));
    dst[lane]      = (signed char)q0;
    dst[lane + 32] = (signed char)q1;
    if (lane < 8) {
        int q2 = min(127, max(-128, (int)rintf(__fdiv_rn(x2, scale))));
        dst[lane + 64] = (signed char)q2;
    } else {
        dst[lane + 64] = 0;   // zero pad bytes 72..95
    }
    if (lane == 0) (t ? g_ks : g_qs)[bh * NTOK + n] = scale;
}

// ---------------- per-channel int8 quant of v (over tokens, transposed) ----------------
__global__ __launch_bounds__(256) void quant_v_kernel()
{
    int col = blockIdx.x;
    int bh = col / HD, d = col % HD;
    int b = bh >> 4, h = bh & 15;
    const float* base = g_qkv + (size_t)b * NTOK * K3 + 2 * CDIM + h * HD + d;

    float vals[8];
    float amax = 0.f;
#pragma unroll
    for (int i = 0; i < 8; i++) {
        vals[i] = base[(size_t)(threadIdx.x + 256 * i) * K3];
        amax = fmaxf(amax, fabsf(vals[i]));
    }
    __shared__ float red[256];
    red[threadIdx.x] = amax;
    __syncthreads();
    for (int s = 128; s >= 1; s >>= 1) {
        if (threadIdx.x < s) red[threadIdx.x] = fmaxf(red[threadIdx.x], red[threadIdx.x + s]);
        __syncthreads();
    }
    float scale = fmaxf(red[0], 1e-8f) / 127.0f;

    signed char* dst = g_v8 + (size_t)(bh * HD + d) * NTOK;
#pragma unroll
    for (int i = 0; i < 8; i++) {
        int m = threadIdx.x + 256 * i;
        int q = min(127, max(-128, (int)rintf(__fdiv_rn(vals[i], scale))));
        dst[m] = (signed char)q;
    }
    if (threadIdx.x == 0) g_vs[bh * HD + d] = scale;
}

// ---------------- int8 QK^T logits GEMM (IMMA m16n8k32), 128x128 tile ----------------
__global__ __launch_bounds__(256) void logits_kernel()
{
    int bh   = blockIdx.z;
    int row0 = blockIdx.y * 128;
    int col0 = blockIdx.x * 128;
    __shared__ char qS[128 * QK_SST];
    __shared__ char kS[128 * QK_SST];

    const int tid = threadIdx.x;
    const char* qg = (const char*)(g_q8 + (size_t)(bh * NTOK + row0) * QK_PAD);
    const char* kg = (const char*)(g_k8 + (size_t)(bh * NTOK + col0) * QK_PAD);
#pragma unroll
    for (int it = 0; it < 3; it++) {
        int idx = tid + it * 256;          // 0..767
        int rr = idx / 6, u = idx % 6;
        *(uint4*)(qS + rr * QK_SST + u * 16) = *(const uint4*)(qg + rr * QK_PAD + u * 16);
        *(uint4*)(kS + rr * QK_SST + u * 16) = *(const uint4*)(kg + rr * QK_PAD + u * 16);
    }
    __syncthreads();

    const int wid = tid >> 5, lane = tid & 31;
    const int lg = lane >> 2, lt = lane & 3;
    const int wm = wid >> 2, wn = wid & 3;    // warp 64x32 tile

    const uint32_t sq = smem_u32(qS);
    const uint32_t sk = smem_u32(kS);
    const uint32_t aBase = sq + (uint32_t)((wm * 64 + lg) * QK_SST + lt * 4);
    const uint32_t bBase = sk + (uint32_t)((wn * 32 + lg) * QK_SST + lt * 4);

    int acc[4][4][4] = {};
#pragma unroll
    for (int k = 0; k < 3; k++) {
        uint32_t bf[4][2];
#pragma unroll
        for (int j = 0; j < 4; j++) {
            uint32_t ba = bBase + (uint32_t)(j * 8 * QK_SST + k * 32);
            bf[j][0] = lds32(ba);
            bf[j][1] = lds32(ba + 16);
        }
#pragma unroll
        for (int i = 0; i < 4; i++) {
            uint32_t aa = aBase + (uint32_t)(i * 16 * QK_SST + k * 32);
            uint32_t a0 = lds32(aa);
            uint32_t a1 = lds32(aa + 8 * QK_SST);
            uint32_t a2 = lds32(aa + 16);
            uint32_t a3 = lds32(aa + 8 * QK_SST + 16);
#pragma unroll
            for (int j = 0; j < 4; j++)
                mma_s8(acc[i][j], a0, a1, a2, a3, bf[j][0], bf[j][1]);
        }
    }

#pragma unroll
    for (int i = 0; i < 4; i++) {
        int r0 = row0 + wm * 64 + i * 16 + lg;
        float qs0 = g_qs[bh * NTOK + r0] * ATT_SCALE;
        float qs1 = g_qs[bh * NTOK + r0 + 8] * ATT_SCALE;
#pragma unroll
        for (int j = 0; j < 4; j++) {
            int cc = col0 + wn * 32 + j * 8 + lt * 2;
            float2 kk = *(const float2*)&g_ks[bh * NTOK + cc];
            float2 v0 = { (float)acc[i][j][0] * qs0 * kk.x, (float)acc[i][j][1] * qs0 * kk.y };
            float2 v1 = { (float)acc[i][j][2] * qs1 * kk.x, (float)acc[i][j][3] * qs1 * kk.y };
            *(float2*)(g_logits + ((size_t)bh * NTOK + r0) * NTOK + cc)       = v0;
            *(float2*)(g_logits + ((size_t)bh * NTOK + r0 + 8) * NTOK + cc)   = v1;
        }
    }
}

// ---------------- softmax + unsigned 8-bit quant per row ----------------
__global__ __launch_bounds__(256) void softmax_kernel()
{
    size_t rowbase = (size_t)blockIdx.x * NTOK;
    const float* lrow = g_logits + rowbase;
    int tid = threadIdx.x;

    float l[8];
    float m = -1e30f;
#pragma unroll
    for (int i = 0; i < 8; i++) {
        l[i] = lrow[tid + 256 * i];
        m = fmaxf(m, l[i]);
    }
    __shared__ float red[256];
    red[tid] = m;
    __syncthreads();
    for (int s = 128; s >= 1; s >>= 1) {
        if (tid < s) red[tid] = fmaxf(red[tid], red[tid + s]);
        __syncthreads();
    }
    m = red[0];
    __syncthreads();

    float e[8];
    float z = 0.f;
#pragma unroll
    for (int i = 0; i < 8; i++) {
        e[i] = expf(l[i] - m);
        z += e[i];
    }
    red[tid] = z;
    __syncthreads();
    for (int s = 128; s >= 1; s >>= 1) {
        if (tid < s) red[tid] += red[tid + s];
        __syncthreads();
    }
    z = red[0];

    unsigned char* prow = g_p8 + rowbase;
#pragma unroll
    for (int i = 0; i < 8; i++) {
        int p = (int)rintf(255.0f * e[i]);
        p = min(255, max(0, p));
        prow[tid + 256 * i] = (unsigned char)p;
    }
    if (tid == 0) g_rowfac[blockIdx.x] = __fdiv_rn(1.0f, z) / 255.0f;
}

// ---------------- PV GEMM (IMMA u8.s8): ctx in split bf16 ----------------
// CTA: 256 q-rows x 72 dims, 8 warps (warp 32x72), k-loop over 2048 in 32-chunks.
#define PV_SST 48
__global__ __launch_bounds__(256, 2) void pv_kernel()
{
    int bh = blockIdx.y;
    int b = bh >> 4, h = bh & 15;
    int row0 = blockIdx.x * 256;

    __shared__ char pS[2][256 * PV_SST];
    __shared__ char vS[2][72 * PV_SST];

    const char* pg = (const char*)(g_p8 + ((size_t)bh * NTOK + row0) * NTOK);
    const char* vg = (const char*)(g_v8 + (size_t)bh * HD * NTOK);

    const int tid = threadIdx.x;
    const int wid = tid >> 5, lane = tid & 31;
    const int lg = lane >> 2, lt = lane & 3;
    const uint32_t sp0 = smem_u32(pS);
    const uint32_t sv0 = smem_u32(vS);

    auto issue = [&](int kc, int buf) {
        // p: 256 rows x 32 bytes -> each thread loads ONE full row (2 x 16B)
        const char* srcp = pg + (size_t)tid * NTOK + kc * 32;
        uint32_t dstp = sp0 + (uint32_t)(buf * 256 * PV_SST + tid * PV_SST);
        cp16(dstp, srcp);
        cp16(dstp + 16, srcp + 16);
        // v: 72 rows x 32 bytes (144 threads, 16B each)
        if (tid < 144) {
            int rr = tid >> 1, u = tid & 1;
            cp16(sv0 + (uint32_t)(buf * 72 * PV_SST + rr * PV_SST + u * 16),
                 vg + (size_t)rr * NTOK + kc * 32 + u * 16);
        }
    };

    int acc[2][9][4] = {};

    issue(0, 0);
    asm volatile("cp.async.commit_group;" ::: "memory");

    for (int kc = 0; kc < 64; kc++) {
        const int buf = kc & 1;
        if (kc + 1 < 64) issue(kc + 1, buf ^ 1);
        asm volatile("cp.async.commit_group;" ::: "memory");
        asm volatile("cp.async.wait_group 1;" ::: "memory");
        __syncthreads();

        const uint32_t ap = sp0 + (uint32_t)(buf * 256 * PV_SST + (wid * 32 + lg) * PV_SST + lt * 4);
        const uint32_t bp = sv0 + (uint32_t)(buf * 72 * PV_SST + lg * PV_SST + lt * 4);

        uint32_t bf[9][2];
#pragma unroll
        for (int j = 0; j < 9; j++) {
            uint32_t ba = bp + (uint32_t)(j * 8 * PV_SST);
            bf[j][0] = lds32(ba);
            bf[j][1] = lds32(ba + 16);
        }
#pragma unroll
        for (int i = 0; i < 2; i++) {
            uint32_t aa = ap + (uint32_t)(i * 16 * PV_SST);
            uint32_t a0 = lds32(aa);
            uint32_t a1 = lds32(aa + 8 * PV_SST);
            uint32_t a2 = lds32(aa + 16);
            uint32_t a3 = lds32(aa + 8 * PV_SST + 16);
#pragma unroll
            for (int j = 0; j < 9; j++)
                mma_u8s8(acc[i][j], a0, a1, a2, a3, bf[j][0], bf[j][1]);
        }
        __syncthreads();
    }

#pragma unroll
    for (int i = 0; i < 2; i++) {
        int n0 = row0 + wid * 32 + i * 16 + lg;
        float rf0 = g_rowfac[bh * NTOK + n0];
        float rf1 = g_rowfac[bh * NTOK + n0 + 8];
#pragma unroll
        for (int j = 0; j < 9; j++) {
            int d = j * 8 + lt * 2;
            float vs0 = g_vs[bh * HD + d];
            float vs1 = g_vs[bh * HD + d + 1];
            float v00 = (float)acc[i][j][0] * rf0 * vs0;
            float v01 = (float)acc[i][j][1] * rf0 * vs1;
            float v10 = (float)acc[i][j][2] * rf1 * vs0;
            float v11 = (float)acc[i][j][3] * rf1 * vs1;
            size_t i0 = (size_t)(b * NTOK + n0) * CDIM + h * HD + d;
            size_t i1 = (size_t)(b * NTOK + n0 + 8) * CDIM + h * HD + d;
            __nv_bfloat16 h00 = __float2bfloat16_rn(v00);
            __nv_bfloat16 h01 = __float2bfloat16_rn(v01);
            __nv_bfloat16 h10 = __float2bfloat16_rn(v10);
            __nv_bfloat16 h11 = __float2bfloat16_rn(v11);
            *(__nv_bfloat162*)&g_ctx_hi[i0] = __nv_bfloat162(h00, h01);
            *(__nv_bfloat162*)&g_ctx_hi[i1] = __nv_bfloat162(h10, h11);
            *(__nv_bfloat162*)&g_ctx_lo[i0] = __nv_bfloat162(
                __float2bfloat16_rn(v00 - __bfloat162float(h00)),
                __float2bfloat16_rn(v01 - __bfloat162float(h01)));
            *(__nv_bfloat162*)&g_ctx_lo[i1] = __nv_bfloat162(
                __float2bfloat16_rn(v10 - __bfloat162float(h10)),
                __float2bfloat16_rn(v11 - __bfloat162float(h11)));
        }
    }
}

// ---------------- launch ----------------
extern "C" void kernel_launch(void* const* d_in, const int* in_sizes, int n_in,
                              void* d_out, int out_size)
{
    const float* x      = (const float*)d_in[0];
    const float* w_qkv  = (const float*)d_in[1];
    const float* w_proj = (const float*)d_in[2];
    const float* b_proj = (const float*)d_in[3];
    float* out = (float*)d_out;
    (void)in_sizes; (void)n_in; (void)out_size;

    void *p_qkv = nullptr;
    void *p_xh = nullptr, *p_xl = nullptr, *p_wqh = nullptr, *p_wql = nullptr;
    void *p_wph = nullptr, *p_wpl = nullptr, *p_cxh = nullptr, *p_cxl = nullptr;
    cudaGetSymbolAddress(&p_qkv, g_qkv);
    cudaGetSymbolAddress(&p_xh, g_x_hi);   cudaGetSymbolAddress(&p_xl, g_x_lo);
    cudaGetSymbolAddress(&p_wqh, g_wq_hi); cudaGetSymbolAddress(&p_wql, g_wq_lo);
    cudaGetSymbolAddress(&p_wph, g_wp_hi); cudaGetSymbolAddress(&p_wpl, g_wp_lo);
    cudaGetSymbolAddress(&p_cxh, g_ctx_hi); cudaGetSymbolAddress(&p_cxl, g_ctx_lo);

    const int GEMM_SMEM = GS * 2 * 128 * SMST * 2;   // 81920
    cudaFuncSetAttribute(hmma_gemm_bf16x3, cudaFuncAttributeMaxDynamicSharedMemorySize, GEMM_SMEM);

    // 0) split fp32 operands into bf16 hi/lo
    {
        int nx = MROWS * CDIM, nq = K3 * CDIM, np = CDIM * CDIM;
        split_kernel<<<(nx + 255) / 256, 256>>>(x, (__nv_bfloat16*)p_xh, (__nv_bfloat16*)p_xl, nx);
        split_kernel<<<(nq + 255) / 256, 256>>>(w_qkv, (__nv_bfloat16*)p_wqh, (__nv_bfloat16*)p_wql, nq);
        split_kernel<<<(np + 255) / 256, 256>>>(w_proj, (__nv_bfloat16*)p_wph, (__nv_bfloat16*)p_wpl, np);
    }

    // 1) QKV projection (HMMA bf16x3): [4096,3456]
    hmma_gemm_bf16x3<<<dim3(K3 / 128, MROWS / 128), 256, GEMM_SMEM>>>(
        (const __nv_bfloat16*)p_xh, (const __nv_bfloat16*)p_xl,
        (const __nv_bfloat16*)p_wqh, (const __nv_bfloat16*)p_wql,
        nullptr, (float*)p_qkv, K3);

    // 2) quantize q,k per row; v per channel
    quant_qk_kernel<<<2 * BH * NTOK / 8, 256>>>();
    quant_v_kernel<<<BH * HD, 256>>>();

    // 3) int8 logits GEMM (IMMA)
    logits_kernel<<<dim3(NTOK / 128, NTOK / 128, BH), 256>>>();

    // 4) softmax + u8 quant
    softmax_kernel<<<BH * NTOK, 256>>>();

    // 5) PV GEMM (IMMA) -> ctx (split bf16)
    pv_kernel<<<dim3(NTOK / 256, BH), 256>>>();

    // 6) output projection + bias (HMMA bf16x3)
    hmma_gemm_bf16x3<<<dim3(CDIM / 128, MROWS / 128), 256, GEMM_SMEM>>>(
        (const __nv_bfloat16*)p_cxh, (const __nv_bfloat16*)p_cxl,
        (const __nv_bfloat16*)p_wph, (const __nv_bfloat16*)p_wpl,
        b_proj, out, CDIM);
}